// round 14
// baseline (speedup 1.0000x reference)
#include <cuda_runtime.h>
#include <cuda_bf16.h>
#include <math.h>
#include <stdint.h>

#define Bn 64
#define Tn 256
#define In 512
#define Hn 800
#define FH 3200   // 4*H

#define NCTA_DIR 67
#define NH 12
#define WCOLS 48

// SMEM geometry for persistent kernel (U slice + 4x z-partials)
#define USTR_B 1616            // bytes per U row (808 bf16), conflict-free
#define U_BYTES (96 * USTR_B)  // 155136
#define ZS_OFF U_BYTES
#define ZSTR 52
#define ZBUF (64 * ZSTR)       // floats per partial buffer
#define LSTM_SMEM (ZS_OFF + 4 * ZBUF * 4)  // 208384

// ---------------- device globals ------------------------------------------
__device__ float g_proj[2][Bn * Tn * FH];
__device__ __nv_bfloat16 g_ahi[8][Bn * Tn * In];
__device__ __nv_bfloat16 g_alo[8][Bn * Tn * In];
__device__ __nv_bfloat16 g_wcat[8][Hn * 1024];
// h in MMA-fragment layout: [dir][buf][hi/lo][k16(50)][bg(4)][r(8)][m(4)][8 bf16]
__device__ __nv_bfloat16 g_hfrag[2][2][2][51200];
__device__ unsigned g_bar_count[2];
__device__ unsigned g_bar_sense[2];

__global__ void init_state() {
    int i = blockIdx.x * blockDim.x + threadIdx.x;
    if (i < Bn * Hn) {
        __nv_bfloat16 z = __float2bfloat16(0.f);
#pragma unroll
        for (int d = 0; d < 2; d++)
#pragma unroll
            for (int bu = 0; bu < 2; bu++)
#pragma unroll
                for (int p = 0; p < 2; p++)
                    g_hfrag[d][bu][p][i] = z;
    }
    if (i < 2) { g_bar_count[i] = 0u; g_bar_sense[i] = 0u; }
}

// ---------------- helpers ---------------------------------------------------
__device__ __forceinline__ uint32_t smem_u32(const void* p) {
    uint32_t a;
    asm("{ .reg .u64 t; cvta.to.shared.u64 t, %1; cvt.u32.u64 %0, t; }" : "=r"(a) : "l"(p));
    return a;
}
__device__ __forceinline__ void ldmatrix_x4(uint32_t& a0, uint32_t& a1, uint32_t& a2, uint32_t& a3,
                                            uint32_t addr) {
    asm volatile("ldmatrix.sync.aligned.m8n8.x4.shared.b16 {%0,%1,%2,%3}, [%4];"
                 : "=r"(a0), "=r"(a1), "=r"(a2), "=r"(a3) : "r"(addr));
}
__device__ __forceinline__ void ldmatrix_x2(uint32_t& b0, uint32_t& b1, uint32_t addr) {
    asm volatile("ldmatrix.sync.aligned.m8n8.x2.shared.b16 {%0,%1}, [%2];"
                 : "=r"(b0), "=r"(b1) : "r"(addr));
}
__device__ __forceinline__ void mma_bf16(float& c0, float& c1, float& c2, float& c3,
                                         uint32_t a0, uint32_t a1, uint32_t a2, uint32_t a3,
                                         uint32_t b0, uint32_t b1) {
    asm volatile("mma.sync.aligned.m16n8k16.row.col.f32.bf16.bf16.f32 "
                 "{%0,%1,%2,%3}, {%4,%5,%6,%7}, {%8,%9}, {%0,%1,%2,%3};"
                 : "+f"(c0), "+f"(c1), "+f"(c2), "+f"(c3)
                 : "r"(a0), "r"(a1), "r"(a2), "r"(a3), "r"(b0), "r"(b1));
}
__device__ __forceinline__ uint4 ldcg_u4(const void* p) {
    uint4 v;
    asm volatile("ld.global.cg.v4.u32 {%0,%1,%2,%3}, [%4];"
                 : "=r"(v.x), "=r"(v.y), "=r"(v.z), "=r"(v.w) : "l"(p));
    return v;
}
__device__ __forceinline__ void cp_async16(uint32_t saddr, const void* gptr) {
    asm volatile("cp.async.cg.shared.global [%0], [%1], 16;" :: "r"(saddr), "l"(gptr));
}
#define CP_COMMIT() asm volatile("cp.async.commit_group;" ::: "memory")
#define CP_WAIT1()  asm volatile("cp.async.wait_group 1;" ::: "memory")

// scoped-atomic grid barrier primitives
__device__ __forceinline__ unsigned atom_add_release_gpu(unsigned* p, unsigned v) {
    unsigned old;
    asm volatile("atom.global.add.release.gpu.u32 %0, [%1], %2;"
                 : "=r"(old) : "l"(p), "r"(v) : "memory");
    return old;
}
__device__ __forceinline__ void st_release_gpu(unsigned* p, unsigned v) {
    asm volatile("st.global.release.gpu.u32 [%0], %1;" :: "l"(p), "r"(v) : "memory");
}
__device__ __forceinline__ unsigned ld_acquire_gpu(const unsigned* p) {
    unsigned v;
    asm volatile("ld.global.acquire.gpu.u32 %0, [%1];" : "=r"(v) : "l"(p) : "memory");
    return v;
}

// ---------------- conversion kernels (unchanged) -----------------------------
__global__ void convert_x(const float* __restrict__ x,
                          const float* __restrict__ mask_f,
                          const float* __restrict__ mask_b)
{
    int idx = blockIdx.x * blockDim.x + threadIdx.x;
    if (idx >= Bn * Tn * (In / 4)) return;
    int bt = idx >> 7;
    int i4 = idx & 127;
    int b  = bt >> 8;
    float4 xv = *(const float4*)(x + (size_t)bt * In + i4 * 4);
#pragma unroll
    for (int dir = 0; dir < 2; dir++) {
        const float* mask = dir ? mask_b : mask_f;
#pragma unroll
        for (int g = 0; g < 4; g++) {
            float4 mv = *(const float4*)(mask + (size_t)b * (4 * In) + (size_t)g * In + i4 * 4);
            float v[4] = {xv.x * mv.x, xv.y * mv.y, xv.z * mv.z, xv.w * mv.w};
            __nv_bfloat16 h[4], l[4];
#pragma unroll
            for (int q = 0; q < 4; q++) {
                h[q] = __float2bfloat16(v[q]);
                l[q] = __float2bfloat16(v[q] - __bfloat162float(h[q]));
            }
            int z = dir * 4 + g;
            size_t o = (size_t)bt * In + i4 * 4;
            __nv_bfloat162 h0; h0.x = h[0]; h0.y = h[1];
            __nv_bfloat162 h1; h1.x = h[2]; h1.y = h[3];
            __nv_bfloat162 l0; l0.x = l[0]; l0.y = l[1];
            __nv_bfloat162 l1; l1.x = l[2]; l1.y = l[3];
            *(__nv_bfloat162*)&g_ahi[z][o]     = h0;
            *(__nv_bfloat162*)&g_ahi[z][o + 2] = h1;
            *(__nv_bfloat162*)&g_alo[z][o]     = l0;
            *(__nv_bfloat162*)&g_alo[z][o + 2] = l1;
        }
    }
}

__global__ void convert_w(const float* __restrict__ W_f,
                          const float* __restrict__ W_b)
{
    int idx = blockIdx.x * blockDim.x + threadIdx.x;
    if (idx >= 8 * In * Hn) return;
    int n    = idx % Hn;
    int rest = idx / Hn;
    int ks   = rest & 511;
    int z    = rest >> 9;
    int dir  = z >> 2, g = z & 3;
    const float* W = dir ? W_b : W_f;
    float v = W[(size_t)ks * FH + (size_t)g * Hn + n];
    __nv_bfloat16 h = __float2bfloat16(v);
    __nv_bfloat16 l = __float2bfloat16(v - __bfloat162float(h));
    g_wcat[z][(size_t)n * 1024 + ks]       = h;
    g_wcat[z][(size_t)n * 1024 + 512 + ks] = l;
}

// ---------------- proj GEMM: mma.sync + 3-stage cp.async pipeline ------------
#define PBK 32
#define PCHUNK 48
#define A_STRIDE 80
#define A_BYTES (128 * A_STRIDE)
#define B_BYTES (80  * A_STRIDE)
#define STAGE_BYTES (A_BYTES + B_BYTES)    // 16640
#define PROJ_SMEM (3 * STAGE_BYTES)        // 49920

__global__ void __launch_bounds__(256)
proj_mma(const float* __restrict__ bias_f, const float* __restrict__ bias_b)
{
    extern __shared__ char psm[];

    const int z   = blockIdx.z;
    const int dir = z >> 2, g = z & 3;
    const int m0  = blockIdx.y * 128;
    const int n0  = blockIdx.x * 80;
    const __nv_bfloat16* __restrict__ ahi = g_ahi[z];
    const __nv_bfloat16* __restrict__ alo = g_alo[z];
    const __nv_bfloat16* __restrict__ wc  = g_wcat[z];
    const float* __restrict__ bias = dir ? bias_b : bias_f;

    const int tid  = threadIdx.x;
    const int wid  = tid >> 5;
    const int lane = tid & 31;
    const int wm   = wid & 3;
    const int wn   = wid >> 2;

    const uint32_t sBase = smem_u32(psm);   // stage s: A at sBase+s*STAGE, B at +A_BYTES

    const int ar0 = (tid) >> 2,        ac0 = (tid) & 3;
    const int ar1 = (tid + 256) >> 2,  ac1 = (tid + 256) & 3;
    const int br0 = (tid) >> 2,        bc0 = (tid) & 3;
    const int br1 = (tid + 256) >> 2,  bc1 = (tid + 256) & 3;
    const int bvalid1 = (tid + 256 < 320);

    // intra-stage ldmatrix offsets
    uint32_t aOffm[2], bOffn[5];
#pragma unroll
    for (int mt = 0; mt < 2; mt++) {
        int row = wm * 32 + mt * 16 + (lane & 15);
        aOffm[mt] = row * A_STRIDE + ((lane >> 4) << 3) * 2;
    }
#pragma unroll
    for (int nt = 0; nt < 5; nt++) {
        int row = wn * 40 + nt * 8 + (lane & 7);
        bOffn[nt] = A_BYTES + row * A_STRIDE + (((lane >> 3) & 1) << 3) * 2;
    }

    float acc[2][5][4];
#pragma unroll
    for (int mt = 0; mt < 2; mt++)
#pragma unroll
        for (int nt = 0; nt < 5; nt++)
#pragma unroll
            for (int q = 0; q < 4; q++) acc[mt][nt][q] = 0.f;

    // stage-fill helper (inlined twice below via lambda-style macro)
#define FILL_STAGE(sidx, cn) do {                                               \
        int ka_, kb_;                                                          \
        const __nv_bfloat16* asrc_;                                            \
        if ((cn) < 16)      { asrc_ = ahi; ka_ = (cn) * PBK;        kb_ = (cn) * PBK; } \
        else if ((cn) < 32) { asrc_ = ahi; ka_ = ((cn) - 16) * PBK; kb_ = (cn) * PBK; } \
        else                { asrc_ = alo; ka_ = ((cn) - 32) * PBK; kb_ = ((cn) - 32) * PBK; } \
        const uint32_t st_ = sBase + (sidx) * STAGE_BYTES;                     \
        cp_async16(st_ + ar0 * A_STRIDE + ac0 * 16, asrc_ + (size_t)(m0 + ar0) * In + ka_ + ac0 * 8); \
        cp_async16(st_ + ar1 * A_STRIDE + ac1 * 16, asrc_ + (size_t)(m0 + ar1) * In + ka_ + ac1 * 8); \
        cp_async16(st_ + A_BYTES + br0 * A_STRIDE + bc0 * 16, wc + (size_t)(n0 + br0) * 1024 + kb_ + bc0 * 8); \
        if (bvalid1)                                                           \
            cp_async16(st_ + A_BYTES + br1 * A_STRIDE + bc1 * 16, wc + (size_t)(n0 + br1) * 1024 + kb_ + bc1 * 8); \
        CP_COMMIT();                                                           \
    } while (0)

    FILL_STAGE(0, 0);
    FILL_STAGE(1, 1);

    for (int c = 0; c < PCHUNK; c++) {
        CP_WAIT1();            // oldest outstanding group (chunk c) complete
        __syncthreads();       // visible to all threads; also retires compute on reused buf

        const uint32_t st = sBase + (c % 3) * STAGE_BYTES;
#pragma unroll
        for (int kk = 0; kk < 2; kk++) {
            uint32_t a[2][4], b[5][2];
#pragma unroll
            for (int mt = 0; mt < 2; mt++)
                ldmatrix_x4(a[mt][0], a[mt][1], a[mt][2], a[mt][3],
                            st + aOffm[mt] + kk * 32);
#pragma unroll
            for (int nt = 0; nt < 5; nt++)
                ldmatrix_x2(b[nt][0], b[nt][1], st + bOffn[nt] + kk * 32);
#pragma unroll
            for (int mt = 0; mt < 2; mt++)
#pragma unroll
                for (int nt = 0; nt < 5; nt++)
                    mma_bf16(acc[mt][nt][0], acc[mt][nt][1], acc[mt][nt][2], acc[mt][nt][3],
                             a[mt][0], a[mt][1], a[mt][2], a[mt][3],
                             b[nt][0], b[nt][1]);
        }

        if (c + 2 < PCHUNK)
            FILL_STAGE((c + 2) % 3, c + 2);
    }
#undef FILL_STAGE

    float* __restrict__ outp = g_proj[dir];
#pragma unroll
    for (int mt = 0; mt < 2; mt++) {
        int mrow0 = m0 + wm * 32 + mt * 16 + (lane >> 2);
#pragma unroll
        for (int nt = 0; nt < 5; nt++) {
            int n = n0 + wn * 40 + nt * 8 + ((lane & 3) << 1);
            float2 bv = *(const float2*)(bias + g * Hn + n);
            float2 v0 = make_float2(acc[mt][nt][0] + bv.x, acc[mt][nt][1] + bv.y);
            float2 v1 = make_float2(acc[mt][nt][2] + bv.x, acc[mt][nt][3] + bv.y);
            *(float2*)(outp + (size_t)mrow0 * FH + (size_t)g * Hn + n) = v0;
            *(float2*)(outp + (size_t)(mrow0 + 8) * FH + (size_t)g * Hn + n) = v1;
        }
    }
}

// ---------------- fast gate nonlinearities ----------------------------------
__device__ __forceinline__ float fast_sigmoid(float x) {
    return __fdividef(1.f, 1.f + __expf(-x));
}
__device__ __forceinline__ float fast_tanh(float x) {
    float e = __expf(2.f * x);
    return 1.f - __fdividef(2.f, e + 1.f);
}

// ---------------- persistent recurrence: 512 threads, 4-way K-split ----------
// 16 warps = 4 M-tiles x 4 K-quarters ({13,13,12,12} k16 blocks). Each warp
// computes all 48 z columns for its k range; 4 SMEM partials reduced in the
// gate phase. 4 warps/SMSP hide LDG/LDSM latency.
__global__ void __launch_bounds__(512, 1)
lstm_persistent(const float* __restrict__ U_f,
                const float* __restrict__ U_b,
                float* __restrict__ out)
{
    extern __shared__ char dsm[];
    char*  sU = dsm;
    float* zs = (float*)(dsm + ZS_OFF);   // [4][64][ZSTR]

    const int bid = blockIdx.x;
    const int dir = bid / NCTA_DIR;
    const int j   = bid - dir * NCTA_DIR;
    const int h0  = j * NH;
    const int tid = threadIdx.x;
    const int lane = tid & 31;
    const int wid = tid >> 5;           // 0..15
    const int wm  = wid & 3;            // M tile (16 batches)
    const int wk  = wid >> 2;           // K quarter
    const float* __restrict__ U = dir ? U_b : U_f;

    // k16 ranges: {13,13,12,12} starting at {0,13,26,38}
    const int kcnt   = (wk < 2) ? 13 : 12;
    const int kstart = wk * 13 - ((wk > 2) ? (wk - 2) : 0);  // 0,13,26,38

    for (int idx = tid; idx < 96 * Hn; idx += 512) {
        int k  = idx / 96;
        int w2 = idx - k * 96;
        int w  = (w2 < 48) ? w2 : w2 - 48;
        int g  = w / NH;
        int c  = w - g * NH;
        int hh = h0 + c;
        float v = (hh < Hn) ? U[(size_t)k * FH + (size_t)g * Hn + hh] : 0.f;
        __nv_bfloat16 hi = __float2bfloat16(v);
        __nv_bfloat16 res = (w2 < 48) ? hi : __float2bfloat16(v - __bfloat162float(hi));
        *(__nv_bfloat16*)(sU + (size_t)w2 * USTR_B + k * 2) = res;
    }

    // gate decode: 768 (b,c) pairs over 512 threads (<=2 each)
    int gb[2], gc2[2], gvalid[2], hoff[2];
#pragma unroll
    for (int it = 0; it < 2; it++) {
        int idx = it * 512 + tid;
        int ok = (idx < Bn * NH) ? 1 : 0;
        if (!ok) idx = 0;
        gb[it]  = idx / NH;
        gc2[it] = idx - gb[it] * NH;
        int hh  = h0 + gc2[it];
        gvalid[it] = ok && (hh < Hn);
        int b = gb[it];
        int k16 = hh >> 4, kin = hh & 15;
        int bg = b >> 4, rr = b & 15;
        hoff[it] = k16 * 1024 + bg * 256 + (rr & 7) * 32 + ((kin & 7) >> 1) * 8
                 + (kin >> 3) * 4 + ((rr >> 3) & 1) * 2 + (kin & 1);
        if (!gvalid[it]) hoff[it] = 0;
    }

    // per-lane A fragment offset within a k16 block
    const int aoff = wm * 256 + (lane >> 2) * 32 + (lane & 3) * 8;
    const int abase = kstart * 1024 + aoff;

    // B ldmatrix addresses at this warp's k origin; x4 folds hi/lo via pt
    const uint32_t sUu = smem_u32(sU);
    uint32_t bAddr[6];
    {
        int l8 = lane & 7;
        int kh = (lane >> 3) & 1;
        int pt = lane >> 4;
#pragma unroll
        for (int nt = 0; nt < 6; nt++)
            bAddr[nt] = sUu + (nt * 8 + l8 + pt * 48) * USTR_B + (kh << 4) + kstart * 32;
    }

    __syncthreads();

    unsigned sense = 0;
    const float* __restrict__ proj = g_proj[dir];

    float c_reg[2] = {0.f, 0.f};
    float pp[2][4];
    {
        const int te = dir ? (Tn - 1) : 0;
#pragma unroll
        for (int it = 0; it < 2; it++) {
            pp[it][0] = pp[it][1] = pp[it][2] = pp[it][3] = 0.f;
            if (gvalid[it]) {
                size_t pbase = ((size_t)gb[it] * Tn + te) * FH + (h0 + gc2[it]);
                pp[it][0] = proj[pbase];
                pp[it][1] = proj[pbase + Hn];
                pp[it][2] = proj[pbase + 2 * Hn];
                pp[it][3] = proj[pbase + 3 * Hn];
            }
        }
    }

    for (int t = 0; t < Tn; t++) {
        const int cur = t & 1;
        const int nxt = cur ^ 1;
        const __nv_bfloat16* __restrict__ fhi = g_hfrag[dir][cur][0];
        const __nv_bfloat16* __restrict__ flo = g_hfrag[dir][cur][1];

        float acc[6][4];
#pragma unroll
        for (int nt = 0; nt < 6; nt++)
#pragma unroll
            for (int q = 0; q < 4; q++) acc[nt][q] = 0.f;

        // depth-2 register prefetch over kcnt k16 blocks
        uint4 AH[2], AL[2];
        AH[0] = ldcg_u4(fhi + abase);
        AL[0] = ldcg_u4(flo + abase);
        AH[1] = ldcg_u4(fhi + abase + 1024);   // kcnt >= 12, always valid
        AL[1] = ldcg_u4(flo + abase + 1024);
#pragma unroll 4
        for (int i = 0; i < kcnt; i++) {
            const int cb = i & 1;
            uint4 ah = AH[cb], al = AL[cb];
            if (i + 2 < kcnt) {
                AH[cb] = ldcg_u4(fhi + abase + (i + 2) * 1024);
                AL[cb] = ldcg_u4(flo + abase + (i + 2) * 1024);
            }
            uint32_t b4[6][4];
#pragma unroll
            for (int nt = 0; nt < 6; nt++)
                ldmatrix_x4(b4[nt][0], b4[nt][1], b4[nt][2], b4[nt][3],
                            bAddr[nt] + i * 32);
#pragma unroll
            for (int nt = 0; nt < 6; nt++) {
                mma_bf16(acc[nt][0], acc[nt][1], acc[nt][2], acc[nt][3],
                         ah.x, ah.y, ah.z, ah.w, b4[nt][0], b4[nt][1]);
                mma_bf16(acc[nt][0], acc[nt][1], acc[nt][2], acc[nt][3],
                         ah.x, ah.y, ah.z, ah.w, b4[nt][2], b4[nt][3]);
                mma_bf16(acc[nt][0], acc[nt][1], acc[nt][2], acc[nt][3],
                         al.x, al.y, al.z, al.w, b4[nt][0], b4[nt][1]);
            }
        }

        // write z partials: wk quarter -> its own buffer
        {
            float* zw = zs + wk * ZBUF;
            int row0 = wm * 16 + (lane >> 2);
            int colb = (lane & 3) << 1;
#pragma unroll
            for (int nt = 0; nt < 6; nt++) {
                int col = colb + nt * 8;
                *(float2*)&zw[row0 * ZSTR + col]       = make_float2(acc[nt][0], acc[nt][1]);
                *(float2*)&zw[(row0 + 8) * ZSTR + col] = make_float2(acc[nt][2], acc[nt][3]);
            }
        }
        __syncthreads();

        __nv_bfloat16* __restrict__ whi = g_hfrag[dir][nxt][0];
        __nv_bfloat16* __restrict__ wlo = g_hfrag[dir][nxt][1];
#pragma unroll
        for (int it = 0; it < 2; it++) {
            if (gvalid[it]) {
                int b  = gb[it];
                int c  = gc2[it];
                int hh = h0 + c;
                float zi = pp[it][0], zf = pp[it][1], zg = pp[it][2], zo = pp[it][3];
#pragma unroll
                for (int q = 0; q < 4; q++) {
                    const float* zq = zs + q * ZBUF + b * ZSTR;
                    zi += zq[0 * NH + c];
                    zf += zq[1 * NH + c];
                    zg += zq[2 * NH + c];
                    zo += zq[3 * NH + c];
                }

                float ig = fast_sigmoid(zi);
                float fg = fast_sigmoid(zf);
                float gg = fast_tanh(zg);
                float og = fast_sigmoid(zo);

                float cv = fg * c_reg[it] + ig * gg;
                float hv = og * fast_tanh(cv);
                c_reg[it] = cv;

                __nv_bfloat16 hvh = __float2bfloat16(hv);
                __nv_bfloat16 hvl = __float2bfloat16(hv - __bfloat162float(hvh));
                whi[hoff[it]] = hvh;
                wlo[hoff[it]] = hvl;

                out[((size_t)b * Tn + t) * (2 * Hn) + (size_t)dir * Hn + hh] = hv;
                if (t == Tn - 1) {
                    size_t hcat0 = (size_t)Bn * Tn * (2 * Hn);
                    size_t ccat0 = hcat0 + (size_t)Bn * (2 * Hn);
                    out[hcat0 + (size_t)b * (2 * Hn) + (size_t)dir * Hn + hh] = hv;
                    out[ccat0 + (size_t)b * (2 * Hn) + (size_t)dir * Hn + hh] = cv;
                }
            }
        }

        // --- release/acquire grid barrier (per direction) ---------------------
        __syncthreads();
        const unsigned ns = sense ^ 1u;
        if (tid == 0) {
            unsigned arrived = atom_add_release_gpu(&g_bar_count[dir], 1u);
            if (arrived == NCTA_DIR - 1) {
                g_bar_count[dir] = 0u;
                st_release_gpu(&g_bar_sense[dir], ns);
            }
        }
        if (t + 1 < Tn) {
            const int te = dir ? (Tn - 2 - t) : (t + 1);
#pragma unroll
            for (int it = 0; it < 2; it++) {
                if (gvalid[it]) {
                    size_t pbase = ((size_t)gb[it] * Tn + te) * FH + (h0 + gc2[it]);
                    pp[it][0] = proj[pbase];
                    pp[it][1] = proj[pbase + Hn];
                    pp[it][2] = proj[pbase + 2 * Hn];
                    pp[it][3] = proj[pbase + 3 * Hn];
                }
            }
        }
        if (lane == 0) {
            while (ld_acquire_gpu(&g_bar_sense[dir]) != ns) __nanosleep(20);
        }
        __syncwarp();
        sense = ns;
    }
}

// ---------------- launch ------------------------------------------------------
extern "C" void kernel_launch(void* const* d_in, const int* in_sizes, int n_in,
                              void* d_out, int out_size)
{
    const float* x      = (const float*)d_in[0];
    const float* mask_f = (const float*)d_in[1];
    const float* mask_b = (const float*)d_in[2];
    const float* W_f    = (const float*)d_in[3];
    const float* U_f    = (const float*)d_in[4];
    const float* b_f    = (const float*)d_in[5];
    const float* W_b    = (const float*)d_in[6];
    const float* U_b    = (const float*)d_in[7];
    const float* b_b    = (const float*)d_in[8];
    float* out = (float*)d_out;

    static int configured = 0;
    if (!configured) {
        cudaFuncSetAttribute(lstm_persistent,
                             cudaFuncAttributeMaxDynamicSharedMemorySize, LSTM_SMEM);
        cudaFuncSetAttribute(proj_mma,
                             cudaFuncAttributeMaxDynamicSharedMemorySize, PROJ_SMEM);
        configured = 1;
    }

    init_state<<<(Bn * Hn + 255) / 256, 256>>>();
    convert_x<<<(Bn * Tn * (In / 4) + 255) / 256, 256>>>(x, mask_f, mask_b);
    convert_w<<<(8 * In * Hn + 255) / 256, 256>>>(W_f, W_b);
    proj_mma<<<dim3(10, 128, 8), 256, PROJ_SMEM>>>(b_f, b_b);
    lstm_persistent<<<2 * NCTA_DIR, 512, LSTM_SMEM>>>(U_f, U_b, out);
}

// round 15
// speedup vs baseline: 1.1104x; 1.1104x over previous
#include <cuda_runtime.h>
#include <cuda_bf16.h>
#include <math.h>
#include <stdint.h>

#define Bn 64
#define Tn 256
#define In 512
#define Hn 800
#define FH 3200   // 4*H

#define NCTA_DIR 67
#define NH 12
#define WCOLS 48

// SMEM geometry for persistent kernel (U slice + 2x z-partials) — R13 config
#define USTR_B 1616            // bytes per U row (808 bf16), conflict-free
#define U_BYTES (96 * USTR_B)  // 155136
#define ZS_OFF U_BYTES
#define ZSTR 52
#define ZBUF (64 * ZSTR)       // floats per partial buffer
#define LSTM_SMEM (ZS_OFF + 2 * ZBUF * 4)  // 181760

// ---------------- device globals ------------------------------------------
__device__ float g_proj[2][Bn * Tn * FH];
__device__ __nv_bfloat16 g_ahi[8][Bn * Tn * In];
__device__ __nv_bfloat16 g_alo[8][Bn * Tn * In];
__device__ __nv_bfloat16 g_wcat[8][Hn * 1024];
// h in MMA-fragment layout: [dir][buf][hi/lo][k16(50)][bg(4)][r(8)][m(4)][8 bf16]
__device__ __nv_bfloat16 g_hfrag[2][2][2][51200];
__device__ unsigned g_bar_count[2];
__device__ unsigned g_bar_sense[2];

__global__ void init_state() {
    int i = blockIdx.x * blockDim.x + threadIdx.x;
    if (i < Bn * Hn) {
        __nv_bfloat16 z = __float2bfloat16(0.f);
#pragma unroll
        for (int d = 0; d < 2; d++)
#pragma unroll
            for (int bu = 0; bu < 2; bu++)
#pragma unroll
                for (int p = 0; p < 2; p++)
                    g_hfrag[d][bu][p][i] = z;
    }
    if (i < 2) { g_bar_count[i] = 0u; g_bar_sense[i] = 0u; }
}

// ---------------- helpers ---------------------------------------------------
__device__ __forceinline__ uint32_t smem_u32(const void* p) {
    uint32_t a;
    asm("{ .reg .u64 t; cvta.to.shared.u64 t, %1; cvt.u32.u64 %0, t; }" : "=r"(a) : "l"(p));
    return a;
}
__device__ __forceinline__ void ldmatrix_x4(uint32_t& a0, uint32_t& a1, uint32_t& a2, uint32_t& a3,
                                            uint32_t addr) {
    asm volatile("ldmatrix.sync.aligned.m8n8.x4.shared.b16 {%0,%1,%2,%3}, [%4];"
                 : "=r"(a0), "=r"(a1), "=r"(a2), "=r"(a3) : "r"(addr));
}
__device__ __forceinline__ void ldmatrix_x2(uint32_t& b0, uint32_t& b1, uint32_t addr) {
    asm volatile("ldmatrix.sync.aligned.m8n8.x2.shared.b16 {%0,%1}, [%2];"
                 : "=r"(b0), "=r"(b1) : "r"(addr));
}
__device__ __forceinline__ void mma_bf16(float& c0, float& c1, float& c2, float& c3,
                                         uint32_t a0, uint32_t a1, uint32_t a2, uint32_t a3,
                                         uint32_t b0, uint32_t b1) {
    asm volatile("mma.sync.aligned.m16n8k16.row.col.f32.bf16.bf16.f32 "
                 "{%0,%1,%2,%3}, {%4,%5,%6,%7}, {%8,%9}, {%0,%1,%2,%3};"
                 : "+f"(c0), "+f"(c1), "+f"(c2), "+f"(c3)
                 : "r"(a0), "r"(a1), "r"(a2), "r"(a3), "r"(b0), "r"(b1));
}
__device__ __forceinline__ uint4 ldcg_u4(const void* p) {
    uint4 v;
    asm volatile("ld.global.cg.v4.u32 {%0,%1,%2,%3}, [%4];"
                 : "=r"(v.x), "=r"(v.y), "=r"(v.z), "=r"(v.w) : "l"(p));
    return v;
}
__device__ __forceinline__ void cp_async16(uint32_t saddr, const void* gptr) {
    asm volatile("cp.async.cg.shared.global [%0], [%1], 16;" :: "r"(saddr), "l"(gptr));
}
#define CP_COMMIT() asm volatile("cp.async.commit_group;" ::: "memory")
#define CP_WAIT1()  asm volatile("cp.async.wait_group 1;" ::: "memory")

// scoped-atomic grid barrier primitives
__device__ __forceinline__ unsigned atom_add_release_gpu(unsigned* p, unsigned v) {
    unsigned old;
    asm volatile("atom.global.add.release.gpu.u32 %0, [%1], %2;"
                 : "=r"(old) : "l"(p), "r"(v) : "memory");
    return old;
}
__device__ __forceinline__ void st_release_gpu(unsigned* p, unsigned v) {
    asm volatile("st.global.release.gpu.u32 [%0], %1;" :: "l"(p), "r"(v) : "memory");
}
__device__ __forceinline__ unsigned ld_acquire_gpu(const unsigned* p) {
    unsigned v;
    asm volatile("ld.global.acquire.gpu.u32 %0, [%1];" : "=r"(v) : "l"(p) : "memory");
    return v;
}

// ---------------- conversion kernels (unchanged) -----------------------------
__global__ void convert_x(const float* __restrict__ x,
                          const float* __restrict__ mask_f,
                          const float* __restrict__ mask_b)
{
    int idx = blockIdx.x * blockDim.x + threadIdx.x;
    if (idx >= Bn * Tn * (In / 4)) return;
    int bt = idx >> 7;
    int i4 = idx & 127;
    int b  = bt >> 8;
    float4 xv = *(const float4*)(x + (size_t)bt * In + i4 * 4);
#pragma unroll
    for (int dir = 0; dir < 2; dir++) {
        const float* mask = dir ? mask_b : mask_f;
#pragma unroll
        for (int g = 0; g < 4; g++) {
            float4 mv = *(const float4*)(mask + (size_t)b * (4 * In) + (size_t)g * In + i4 * 4);
            float v[4] = {xv.x * mv.x, xv.y * mv.y, xv.z * mv.z, xv.w * mv.w};
            __nv_bfloat16 h[4], l[4];
#pragma unroll
            for (int q = 0; q < 4; q++) {
                h[q] = __float2bfloat16(v[q]);
                l[q] = __float2bfloat16(v[q] - __bfloat162float(h[q]));
            }
            int z = dir * 4 + g;
            size_t o = (size_t)bt * In + i4 * 4;
            __nv_bfloat162 h0; h0.x = h[0]; h0.y = h[1];
            __nv_bfloat162 h1; h1.x = h[2]; h1.y = h[3];
            __nv_bfloat162 l0; l0.x = l[0]; l0.y = l[1];
            __nv_bfloat162 l1; l1.x = l[2]; l1.y = l[3];
            *(__nv_bfloat162*)&g_ahi[z][o]     = h0;
            *(__nv_bfloat162*)&g_ahi[z][o + 2] = h1;
            *(__nv_bfloat162*)&g_alo[z][o]     = l0;
            *(__nv_bfloat162*)&g_alo[z][o + 2] = l1;
        }
    }
}

__global__ void convert_w(const float* __restrict__ W_f,
                          const float* __restrict__ W_b)
{
    int idx = blockIdx.x * blockDim.x + threadIdx.x;
    if (idx >= 8 * In * Hn) return;
    int n    = idx % Hn;
    int rest = idx / Hn;
    int ks   = rest & 511;
    int z    = rest >> 9;
    int dir  = z >> 2, g = z & 3;
    const float* W = dir ? W_b : W_f;
    float v = W[(size_t)ks * FH + (size_t)g * Hn + n];
    __nv_bfloat16 h = __float2bfloat16(v);
    __nv_bfloat16 l = __float2bfloat16(v - __bfloat162float(h));
    g_wcat[z][(size_t)n * 1024 + ks]       = h;
    g_wcat[z][(size_t)n * 1024 + 512 + ks] = l;
}

// ---------------- proj GEMM v2: 256x160 CTA tile, 512 thr, 3-stage cp.async ---
// Halves chip L2 traffic vs the 128x80 tile (A re-read 5x not 10x; B 64x not 128x).
#define PBK 32
#define PCHUNK 48
#define PA_STRIDE 80
#define PA_BYTES (256 * PA_STRIDE)     // 20480
#define PB_BYTES (160 * PA_STRIDE)     // 12800
#define PSTAGE (PA_BYTES + PB_BYTES)   // 33280
#define PROJ_SMEM (3 * PSTAGE)         // 99840

__global__ void __launch_bounds__(512, 1)
proj_mma(const float* __restrict__ bias_f, const float* __restrict__ bias_b)
{
    extern __shared__ char psm[];

    const int z   = blockIdx.z;
    const int dir = z >> 2, g = z & 3;
    const int m0  = blockIdx.y * 256;
    const int n0  = blockIdx.x * 160;
    const __nv_bfloat16* __restrict__ ahi = g_ahi[z];
    const __nv_bfloat16* __restrict__ alo = g_alo[z];
    const __nv_bfloat16* __restrict__ wc  = g_wcat[z];
    const float* __restrict__ bias = dir ? bias_b : bias_f;

    const int tid  = threadIdx.x;
    const int wid  = tid >> 5;
    const int lane = tid & 31;
    const int wm   = wid & 3;          // 4 M sub-tiles of 64 rows
    const int wn   = wid >> 2;         // 4 N groups of 40 cols

    const uint32_t sBase = smem_u32(psm);

    // staging decode: 4 iters x 512 threads = 2048 slots; A = 1024 uint4, B = 640
    int s_isA[4], s_r[4], s_c[4], s_valid[4];
#pragma unroll
    for (int i = 0; i < 4; i++) {
        int idx = tid + i * 512;
        if (idx < 1024) { s_isA[i] = 1; s_r[i] = idx >> 2; s_c[i] = idx & 3; s_valid[i] = 1; }
        else {
            int jj = idx - 1024;
            s_isA[i] = 0; s_r[i] = jj >> 2; s_c[i] = jj & 3; s_valid[i] = (jj < 640);
        }
    }

    // intra-stage ldmatrix offsets
    uint32_t aOffm[4], bOffn[5];
#pragma unroll
    for (int mt = 0; mt < 4; mt++) {
        int row = wm * 64 + mt * 16 + (lane & 15);
        aOffm[mt] = row * PA_STRIDE + ((lane >> 4) << 4);
    }
#pragma unroll
    for (int nt = 0; nt < 5; nt++) {
        int row = wn * 40 + nt * 8 + (lane & 7);
        bOffn[nt] = PA_BYTES + row * PA_STRIDE + (((lane >> 3) & 1) << 4);
    }

    float acc[4][5][4];
#pragma unroll
    for (int mt = 0; mt < 4; mt++)
#pragma unroll
        for (int nt = 0; nt < 5; nt++)
#pragma unroll
            for (int q = 0; q < 4; q++) acc[mt][nt][q] = 0.f;

#define FILL_STAGE(sidx, cn) do {                                                \
        int ka_, kb_;                                                           \
        const __nv_bfloat16* asrc_;                                             \
        if ((cn) < 16)      { asrc_ = ahi; ka_ = (cn) * PBK;        kb_ = (cn) * PBK; } \
        else if ((cn) < 32) { asrc_ = ahi; ka_ = ((cn) - 16) * PBK; kb_ = (cn) * PBK; } \
        else                { asrc_ = alo; ka_ = ((cn) - 32) * PBK; kb_ = ((cn) - 32) * PBK; } \
        const uint32_t st_ = sBase + (sidx) * PSTAGE;                           \
        _Pragma("unroll")                                                       \
        for (int i_ = 0; i_ < 4; i_++) {                                        \
            if (s_valid[i_]) {                                                  \
                if (s_isA[i_])                                                  \
                    cp_async16(st_ + s_r[i_] * PA_STRIDE + s_c[i_] * 16,        \
                               asrc_ + (size_t)(m0 + s_r[i_]) * In + ka_ + s_c[i_] * 8); \
                else                                                            \
                    cp_async16(st_ + PA_BYTES + s_r[i_] * PA_STRIDE + s_c[i_] * 16, \
                               wc + (size_t)(n0 + s_r[i_]) * 1024 + kb_ + s_c[i_] * 8); \
            }                                                                   \
        }                                                                       \
        CP_COMMIT();                                                            \
    } while (0)

    FILL_STAGE(0, 0);
    FILL_STAGE(1, 1);

    for (int c = 0; c < PCHUNK; c++) {
        CP_WAIT1();
        __syncthreads();

        const uint32_t st = sBase + (c % 3) * PSTAGE;
#pragma unroll
        for (int kk = 0; kk < 2; kk++) {
            uint32_t a[4][4], b[5][2];
#pragma unroll
            for (int mt = 0; mt < 4; mt++)
                ldmatrix_x4(a[mt][0], a[mt][1], a[mt][2], a[mt][3],
                            st + aOffm[mt] + kk * 32);
#pragma unroll
            for (int nt = 0; nt < 5; nt++)
                ldmatrix_x2(b[nt][0], b[nt][1], st + bOffn[nt] + kk * 32);
#pragma unroll
            for (int mt = 0; mt < 4; mt++)
#pragma unroll
                for (int nt = 0; nt < 5; nt++)
                    mma_bf16(acc[mt][nt][0], acc[mt][nt][1], acc[mt][nt][2], acc[mt][nt][3],
                             a[mt][0], a[mt][1], a[mt][2], a[mt][3],
                             b[nt][0], b[nt][1]);
        }

        if (c + 2 < PCHUNK)
            FILL_STAGE((c + 2) % 3, c + 2);
    }
#undef FILL_STAGE

    float* __restrict__ outp = g_proj[dir];
#pragma unroll
    for (int mt = 0; mt < 4; mt++) {
        int mrow0 = m0 + wm * 64 + mt * 16 + (lane >> 2);
#pragma unroll
        for (int nt = 0; nt < 5; nt++) {
            int n = n0 + wn * 40 + nt * 8 + ((lane & 3) << 1);
            float2 bv = *(const float2*)(bias + g * Hn + n);
            float2 v0 = make_float2(acc[mt][nt][0] + bv.x, acc[mt][nt][1] + bv.y);
            float2 v1 = make_float2(acc[mt][nt][2] + bv.x, acc[mt][nt][3] + bv.y);
            *(float2*)(outp + (size_t)mrow0 * FH + (size_t)g * Hn + n) = v0;
            *(float2*)(outp + (size_t)(mrow0 + 8) * FH + (size_t)g * Hn + n) = v1;
        }
    }
}

// ---------------- fast gate nonlinearities ----------------------------------
__device__ __forceinline__ float fast_sigmoid(float x) {
    return __fdividef(1.f, 1.f + __expf(-x));
}
__device__ __forceinline__ float fast_tanh(float x) {
    float e = __expf(2.f * x);
    return 1.f - __fdividef(2.f, e + 1.f);
}

// ---------------- persistent recurrence: R13 config (verbatim) ---------------
__global__ void __launch_bounds__(256, 1)
lstm_persistent(const float* __restrict__ U_f,
                const float* __restrict__ U_b,
                float* __restrict__ out)
{
    extern __shared__ char dsm[];
    char*  sU = dsm;
    float* zs = (float*)(dsm + ZS_OFF);   // [2][64][ZSTR]

    const int bid = blockIdx.x;
    const int dir = bid / NCTA_DIR;
    const int j   = bid - dir * NCTA_DIR;
    const int h0  = j * NH;
    const int tid = threadIdx.x;
    const int lane = tid & 31;
    const int wid = tid >> 5;
    const int wm  = wid & 3;
    const int wn  = wid >> 2;
    const float* __restrict__ U = dir ? U_b : U_f;

    for (int idx = tid; idx < 96 * Hn; idx += 256) {
        int k  = idx / 96;
        int w2 = idx - k * 96;
        int w  = (w2 < 48) ? w2 : w2 - 48;
        int g  = w / NH;
        int c  = w - g * NH;
        int hh = h0 + c;
        float v = (hh < Hn) ? U[(size_t)k * FH + (size_t)g * Hn + hh] : 0.f;
        __nv_bfloat16 hi = __float2bfloat16(v);
        __nv_bfloat16 res = (w2 < 48) ? hi : __float2bfloat16(v - __bfloat162float(hi));
        *(__nv_bfloat16*)(sU + (size_t)w2 * USTR_B + k * 2) = res;
    }

    int gb[3], gc2[3], gvalid[3], hoff[3];
#pragma unroll
    for (int it = 0; it < 3; it++) {
        int idx = it * 256 + tid;
        gb[it]  = idx / NH;
        gc2[it] = idx - gb[it] * NH;
        int hh  = h0 + gc2[it];
        gvalid[it] = (hh < Hn) ? 1 : 0;
        int b = gb[it];
        int k16 = hh >> 4, kin = hh & 15;
        int bg = b >> 4, rr = b & 15;
        hoff[it] = k16 * 1024 + bg * 256 + (rr & 7) * 32 + ((kin & 7) >> 1) * 8
                 + (kin >> 3) * 4 + ((rr >> 3) & 1) * 2 + (kin & 1);
        if (!gvalid[it]) hoff[it] = 0;
    }

    const int aoff = wm * 256 + (lane >> 2) * 32 + (lane & 3) * 8;
    const int kbase16 = wn * 25;
    const int abase = kbase16 * 1024 + aoff;

    const uint32_t sUu = smem_u32(sU);
    uint32_t bAddr[6];
    {
        int l8 = lane & 7;
        int kh = (lane >> 3) & 1;
        int pt = lane >> 4;
#pragma unroll
        for (int nt = 0; nt < 6; nt++)
            bAddr[nt] = sUu + (nt * 8 + l8 + pt * 48) * USTR_B + (kh << 4) + kbase16 * 32;
    }

    __syncthreads();

    unsigned sense = 0;
    const float* __restrict__ proj = g_proj[dir];

    float c_reg[3] = {0.f, 0.f, 0.f};
    float pp[3][4];
    {
        const int te = dir ? (Tn - 1) : 0;
#pragma unroll
        for (int it = 0; it < 3; it++) {
            pp[it][0] = pp[it][1] = pp[it][2] = pp[it][3] = 0.f;
            if (gvalid[it]) {
                size_t pbase = ((size_t)gb[it] * Tn + te) * FH + (h0 + gc2[it]);
                pp[it][0] = proj[pbase];
                pp[it][1] = proj[pbase + Hn];
                pp[it][2] = proj[pbase + 2 * Hn];
                pp[it][3] = proj[pbase + 3 * Hn];
            }
        }
    }

    for (int t = 0; t < Tn; t++) {
        const int cur = t & 1;
        const int nxt = cur ^ 1;
        const __nv_bfloat16* __restrict__ fhi = g_hfrag[dir][cur][0];
        const __nv_bfloat16* __restrict__ flo = g_hfrag[dir][cur][1];

        float acc[6][4];
#pragma unroll
        for (int nt = 0; nt < 6; nt++)
#pragma unroll
            for (int q = 0; q < 4; q++) acc[nt][q] = 0.f;

        uint4 Ah[2][5], Al[2][5];
#pragma unroll
        for (int j2 = 0; j2 < 5; j2++) {
            Ah[0][j2] = ldcg_u4(fhi + abase + j2 * 1024);
            Al[0][j2] = ldcg_u4(flo + abase + j2 * 1024);
        }
#pragma unroll
        for (int c = 0; c < 5; c++) {
            const int cb = c & 1, nb = cb ^ 1;
            if (c < 4) {
#pragma unroll
                for (int j2 = 0; j2 < 5; j2++) {
                    int kb = (c + 1) * 5 + j2;
                    Ah[nb][j2] = ldcg_u4(fhi + abase + kb * 1024);
                    Al[nb][j2] = ldcg_u4(flo + abase + kb * 1024);
                }
            }
#pragma unroll
            for (int j2 = 0; j2 < 5; j2++) {
                const int klocal = c * 5 + j2;
                uint32_t b4[6][4];
#pragma unroll
                for (int nt = 0; nt < 6; nt++)
                    ldmatrix_x4(b4[nt][0], b4[nt][1], b4[nt][2], b4[nt][3],
                                bAddr[nt] + klocal * 32);
#pragma unroll
                for (int nt = 0; nt < 6; nt++) {
                    mma_bf16(acc[nt][0], acc[nt][1], acc[nt][2], acc[nt][3],
                             Ah[cb][j2].x, Ah[cb][j2].y, Ah[cb][j2].z, Ah[cb][j2].w,
                             b4[nt][0], b4[nt][1]);
                    mma_bf16(acc[nt][0], acc[nt][1], acc[nt][2], acc[nt][3],
                             Ah[cb][j2].x, Ah[cb][j2].y, Ah[cb][j2].z, Ah[cb][j2].w,
                             b4[nt][2], b4[nt][3]);
                    mma_bf16(acc[nt][0], acc[nt][1], acc[nt][2], acc[nt][3],
                             Al[cb][j2].x, Al[cb][j2].y, Al[cb][j2].z, Al[cb][j2].w,
                             b4[nt][0], b4[nt][1]);
                }
            }
        }

        {
            float* zw = zs + wn * ZBUF;
            int row0 = wm * 16 + (lane >> 2);
            int colb = (lane & 3) << 1;
#pragma unroll
            for (int nt = 0; nt < 6; nt++) {
                int col = colb + nt * 8;
                *(float2*)&zw[row0 * ZSTR + col]       = make_float2(acc[nt][0], acc[nt][1]);
                *(float2*)&zw[(row0 + 8) * ZSTR + col] = make_float2(acc[nt][2], acc[nt][3]);
            }
        }
        __syncthreads();

        __nv_bfloat16* __restrict__ whi = g_hfrag[dir][nxt][0];
        __nv_bfloat16* __restrict__ wlo = g_hfrag[dir][nxt][1];
#pragma unroll
        for (int it = 0; it < 3; it++) {
            if (gvalid[it]) {
                int b  = gb[it];
                int c  = gc2[it];
                int hh = h0 + c;
                float zi = zs[b * ZSTR + 0 * NH + c] + zs[ZBUF + b * ZSTR + 0 * NH + c] + pp[it][0];
                float zf = zs[b * ZSTR + 1 * NH + c] + zs[ZBUF + b * ZSTR + 1 * NH + c] + pp[it][1];
                float zg = zs[b * ZSTR + 2 * NH + c] + zs[ZBUF + b * ZSTR + 2 * NH + c] + pp[it][2];
                float zo = zs[b * ZSTR + 3 * NH + c] + zs[ZBUF + b * ZSTR + 3 * NH + c] + pp[it][3];

                float ig = fast_sigmoid(zi);
                float fg = fast_sigmoid(zf);
                float gg = fast_tanh(zg);
                float og = fast_sigmoid(zo);

                float cv = fg * c_reg[it] + ig * gg;
                float hv = og * fast_tanh(cv);
                c_reg[it] = cv;

                __nv_bfloat16 hvh = __float2bfloat16(hv);
                __nv_bfloat16 hvl = __float2bfloat16(hv - __bfloat162float(hvh));
                whi[hoff[it]] = hvh;
                wlo[hoff[it]] = hvl;

                out[((size_t)b * Tn + t) * (2 * Hn) + (size_t)dir * Hn + hh] = hv;
                if (t == Tn - 1) {
                    size_t hcat0 = (size_t)Bn * Tn * (2 * Hn);
                    size_t ccat0 = hcat0 + (size_t)Bn * (2 * Hn);
                    out[hcat0 + (size_t)b * (2 * Hn) + (size_t)dir * Hn + hh] = hv;
                    out[ccat0 + (size_t)b * (2 * Hn) + (size_t)dir * Hn + hh] = cv;
                }
            }
        }

        // --- release/acquire grid barrier (per direction) ---------------------
        __syncthreads();
        const unsigned ns = sense ^ 1u;
        if (tid == 0) {
            unsigned arrived = atom_add_release_gpu(&g_bar_count[dir], 1u);
            if (arrived == NCTA_DIR - 1) {
                g_bar_count[dir] = 0u;
                st_release_gpu(&g_bar_sense[dir], ns);
            }
        }
        if (t + 1 < Tn) {
            const int te = dir ? (Tn - 2 - t) : (t + 1);
#pragma unroll
            for (int it = 0; it < 3; it++) {
                if (gvalid[it]) {
                    size_t pbase = ((size_t)gb[it] * Tn + te) * FH + (h0 + gc2[it]);
                    pp[it][0] = proj[pbase];
                    pp[it][1] = proj[pbase + Hn];
                    pp[it][2] = proj[pbase + 2 * Hn];
                    pp[it][3] = proj[pbase + 3 * Hn];
                }
            }
        }
        if (lane == 0) {
            while (ld_acquire_gpu(&g_bar_sense[dir]) != ns) __nanosleep(20);
        }
        __syncwarp();
        sense = ns;
    }
}

// ---------------- launch ------------------------------------------------------
extern "C" void kernel_launch(void* const* d_in, const int* in_sizes, int n_in,
                              void* d_out, int out_size)
{
    const float* x      = (const float*)d_in[0];
    const float* mask_f = (const float*)d_in[1];
    const float* mask_b = (const float*)d_in[2];
    const float* W_f    = (const float*)d_in[3];
    const float* U_f    = (const float*)d_in[4];
    const float* b_f    = (const float*)d_in[5];
    const float* W_b    = (const float*)d_in[6];
    const float* U_b    = (const float*)d_in[7];
    const float* b_b    = (const float*)d_in[8];
    float* out = (float*)d_out;

    static int configured = 0;
    if (!configured) {
        cudaFuncSetAttribute(lstm_persistent,
                             cudaFuncAttributeMaxDynamicSharedMemorySize, LSTM_SMEM);
        cudaFuncSetAttribute(proj_mma,
                             cudaFuncAttributeMaxDynamicSharedMemorySize, PROJ_SMEM);
        configured = 1;
    }

    init_state<<<(Bn * Hn + 255) / 256, 256>>>();
    convert_x<<<(Bn * Tn * (In / 4) + 255) / 256, 256>>>(x, mask_f, mask_b);
    convert_w<<<(8 * In * Hn + 255) / 256, 256>>>(W_f, W_b);
    proj_mma<<<dim3(5, 64, 8), 512, PROJ_SMEM>>>(b_f, b_b);
    lstm_persistent<<<2 * NCTA_DIR, 256, LSTM_SMEM>>>(U_f, U_b, out);
}